// round 1
// baseline (speedup 1.0000x reference)
#include <cuda_runtime.h>
#include <cstdint>

// ---------------------------------------------------------------------------
// Problem constants
//   image [16,3,256,256] -> conv1 s2 -> [16,192,128,128] relu
//                        -> conv2 s2 -> [16,384,64,64]   relu
//                        -> conv3 s2 -> [16,768,32,32]
//   feats [16,1024,768]; distances to codebook[8192,768]; argmin -> tokens
//   embeddings = embedding_table[tokens]
// Output (assumed): float32 [ tokens(16384) | embeddings(16*1024*768) ]
// ---------------------------------------------------------------------------

// Scratch (device globals: allocation-free per harness rules)
__device__ float g_f1[16u * 192u * 128u * 128u];   // 201 MB
__device__ float g_f2[16u * 384u * 64u * 64u];     // 100 MB
__device__ float g_f3[16u * 768u * 1024u];         //  50 MB
__device__ float g_c2h[8192];                      // 0.5*||c||^2
__device__ unsigned long long g_best[16384];       // packed (score, ~idx)

// ---------------------------------------------------------------------------
// 0.5 * ||codebook_v||^2, one warp per row
// ---------------------------------------------------------------------------
__global__ void c2half_kernel(const float* __restrict__ cb) {
    int v = blockIdx.x * 8 + (threadIdx.x >> 5);
    int lane = threadIdx.x & 31;
    const float* row = cb + (size_t)v * 768;
    float s = 0.f;
    for (int c = lane; c < 768; c += 32) { float t = row[c]; s = fmaf(t, t, s); }
#pragma unroll
    for (int o = 16; o > 0; o >>= 1) s += __shfl_xor_sync(0xFFFFFFFFu, s, o);
    if (lane == 0) g_c2h[v] = 0.5f * s;
}

__global__ void init_best_kernel() {
    int i = blockIdx.x * 256 + threadIdx.x;
    if (i < 16384) g_best[i] = 0ULL;
}

// ---------------------------------------------------------------------------
// conv1: Cin=3, 3x3 s2 pad1, relu. Thread computes 4 consecutive x outputs,
// loops all 192 output channels with weights in smem.
// ---------------------------------------------------------------------------
__global__ __launch_bounds__(128) void conv1_kernel(
    const float* __restrict__ in, const float* __restrict__ w,
    const float* __restrict__ bias)
{
    __shared__ float Ws[192 * 27];
    __shared__ float Bsm[192];
    for (int i = threadIdx.x; i < 192 * 27; i += 128) Ws[i] = w[i];
    for (int i = threadIdx.x; i < 192; i += 128) Bsm[i] = bias[i];
    __syncthreads();

    int g = blockIdx.x * 128 + threadIdx.x;     // 65536 groups
    int x0 = (g & 31) * 4;
    int y = (g >> 5) & 127;
    int b = g >> 12;

    float xv[3][3][9];
    int iy0 = 2 * y - 1;
    int ix0 = 2 * x0 - 1;
#pragma unroll
    for (int ci = 0; ci < 3; ci++)
#pragma unroll
        for (int ky = 0; ky < 3; ky++) {
            int iy = iy0 + ky;
            bool yok = (iy >= 0) && (iy < 256);
            const float* rowp = in + (((size_t)b * 3 + ci) * 256 + iy) * 256;
#pragma unroll
            for (int c = 0; c < 9; c++) {
                int ix = ix0 + c;
                xv[ci][ky][c] = (yok && ix >= 0 && ix < 256) ? rowp[ix] : 0.f;
            }
        }

    float* outp = g_f1 + (size_t)b * 192 * 16384 + y * 128 + x0;
    for (int co = 0; co < 192; co++) {
        float bv = Bsm[co];
        float a0 = bv, a1 = bv, a2 = bv, a3 = bv;
        const float* wp = &Ws[co * 27];
#pragma unroll
        for (int ci = 0; ci < 3; ci++)
#pragma unroll
            for (int ky = 0; ky < 3; ky++)
#pragma unroll
                for (int kx = 0; kx < 3; kx++) {
                    float wv = wp[ci * 9 + ky * 3 + kx];
                    a0 = fmaf(wv, xv[ci][ky][0 + kx], a0);
                    a1 = fmaf(wv, xv[ci][ky][2 + kx], a1);
                    a2 = fmaf(wv, xv[ci][ky][4 + kx], a2);
                    a3 = fmaf(wv, xv[ci][ky][6 + kx], a3);
                }
        float4 r;
        r.x = fmaxf(a0, 0.f); r.y = fmaxf(a1, 0.f);
        r.z = fmaxf(a2, 0.f); r.w = fmaxf(a3, 0.f);
        *(float4*)(outp + (size_t)co * 16384) = r;
    }
}

// ---------------------------------------------------------------------------
// 128x128x8 double-buffered fp32 GEMM.
//  GATHER=true : B tile gathered from NCHW feature map (implicit-GEMM conv,
//                3x3 s2 pad1). A = weights [M][K=Cin*9]. C += bias, opt relu.
//  GATHER=false: B = f3 [batch][K][1024] (codebook distance). ARGMAX epilogue
//                reduces max(score - 0.5||c||^2) into g_best (packed keys).
// ---------------------------------------------------------------------------
__device__ __forceinline__ unsigned long long pack_key(float s, int v) {
    unsigned u = __float_as_uint(s);
    u = (u & 0x80000000u) ? ~u : (u | 0x80000000u);
    return ((unsigned long long)u << 32) | (unsigned)(0xFFFFFFFFu - (unsigned)v);
}

template<bool GATHER, bool RELU, bool ARGMAX, int CIN, int HIN, int WIN, int HOUT, int WOUT>
__global__ __launch_bounds__(256)
void gemm128_kernel(const float* __restrict__ A,
                    const float* __restrict__ Bsrc,
                    const float* __restrict__ bias,
                    float* __restrict__ Cdst,
                    int M, int N, int K)
{
    __shared__ float As[2][8][128];
    __shared__ float Bs[2][8][128];
    __shared__ unsigned long long red[128];

    const int tid = threadIdx.x;
    const int m0 = blockIdx.x * 128;
    const int n0 = blockIdx.y * 128;
    const int tm = tid & 15;
    const int tn = tid >> 4;

    float acc[8][8];
#pragma unroll
    for (int i = 0; i < 8; i++)
#pragma unroll
        for (int j = 0; j < 8; j++) acc[i][j] = 0.f;

    // A tile loader: thread -> (row tid>>1, 4 consecutive k)
    const int a_m = tid >> 1;
    const int a_k = (tid & 1) * 4;
    const float* Aptr = A + (size_t)(m0 + a_m) * K + a_k;

    // B tile loader setup
    int by = 0, bx = 0;
    const float* Bbase = Bsrc;
    if constexpr (GATHER) {
        const int hw = HOUT * WOUT;
        int n = n0 + (tid & 127);
        int bb = n / hw;
        int rem = n - bb * hw;
        by = rem / WOUT;
        bx = rem - by * WOUT;
        Bbase = Bsrc + (size_t)bb * CIN * HIN * WIN;
    } else {
        int n = n0 + (tid & 31) * 4;
        int bb = n >> 10;
        int p = n & 1023;
        Bbase = Bsrc + (size_t)bb * K * 1024 + p;
    }

    const int nT = K >> 3;
    float4 areg, breg4;
    float bregs[4];

    // ---- prologue: chunk 0 -> regs -> smem[0]
    areg = *(const float4*)(Aptr);
    if constexpr (GATHER) {
#pragma unroll
        for (int s = 0; s < 4; s++) {
            int k = (tid >> 7) + s * 2;
            int ci = (k * 7282) >> 16;                 // k/9, exact for k<32768
            int r = k - ci * 9;
            int ky = (r * 11) >> 5;                    // r/3 for r<9
            int kx = r - ky * 3;
            int iy = 2 * by - 1 + ky;
            int ix = 2 * bx - 1 + kx;
            bool ok = (iy >= 0) && (iy < HIN) && (ix >= 0) && (ix < WIN);
            bregs[s] = ok ? Bbase[(size_t)(ci * HIN + iy) * WIN + ix] : 0.f;
        }
    } else {
        breg4 = *(const float4*)(Bbase + (size_t)(tid >> 5) * 1024);
    }
    As[0][a_k + 0][a_m] = areg.x;
    As[0][a_k + 1][a_m] = areg.y;
    As[0][a_k + 2][a_m] = areg.z;
    As[0][a_k + 3][a_m] = areg.w;
    if constexpr (GATHER) {
#pragma unroll
        for (int s = 0; s < 4; s++)
            Bs[0][(tid >> 7) + s * 2][tid & 127] = bregs[s];
    } else {
        *(float4*)&Bs[0][tid >> 5][(tid & 31) * 4] = breg4;
    }
    __syncthreads();

    // ---- main loop
    for (int kt = 0; kt < nT; kt++) {
        const int buf = kt & 1;
        if (kt + 1 < nT) {
            const int kNext = (kt + 1) * 8;
            areg = *(const float4*)(Aptr + kNext);
            if constexpr (GATHER) {
#pragma unroll
                for (int s = 0; s < 4; s++) {
                    int k = kNext + (tid >> 7) + s * 2;
                    int ci = (k * 7282) >> 16;
                    int r = k - ci * 9;
                    int ky = (r * 11) >> 5;
                    int kx = r - ky * 3;
                    int iy = 2 * by - 1 + ky;
                    int ix = 2 * bx - 1 + kx;
                    bool ok = (iy >= 0) && (iy < HIN) && (ix >= 0) && (ix < WIN);
                    bregs[s] = ok ? Bbase[(size_t)(ci * HIN + iy) * WIN + ix] : 0.f;
                }
            } else {
                breg4 = *(const float4*)(Bbase + (size_t)(kNext + (tid >> 5)) * 1024);
            }
        }
#pragma unroll
        for (int kk = 0; kk < 8; kk++) {
            float4 A0 = *(const float4*)&As[buf][kk][tm * 4];
            float4 A1 = *(const float4*)&As[buf][kk][64 + tm * 4];
            float4 B0 = *(const float4*)&Bs[buf][kk][tn * 4];
            float4 B1 = *(const float4*)&Bs[buf][kk][64 + tn * 4];
            float av[8] = {A0.x, A0.y, A0.z, A0.w, A1.x, A1.y, A1.z, A1.w};
            float bv[8] = {B0.x, B0.y, B0.z, B0.w, B1.x, B1.y, B1.z, B1.w};
#pragma unroll
            for (int i = 0; i < 8; i++)
#pragma unroll
                for (int j = 0; j < 8; j++)
                    acc[i][j] = fmaf(av[i], bv[j], acc[i][j]);
        }
        if (kt + 1 < nT) {
            const int nb = buf ^ 1;
            As[nb][a_k + 0][a_m] = areg.x;
            As[nb][a_k + 1][a_m] = areg.y;
            As[nb][a_k + 2][a_m] = areg.z;
            As[nb][a_k + 3][a_m] = areg.w;
            if constexpr (GATHER) {
#pragma unroll
                for (int s = 0; s < 4; s++)
                    Bs[nb][(tid >> 7) + s * 2][tid & 127] = bregs[s];
            } else {
                *(float4*)&Bs[nb][tid >> 5][(tid & 31) * 4] = breg4;
            }
            __syncthreads();
        }
    }

    // ---- epilogue
    if constexpr (!ARGMAX) {
        const int HW = HOUT * WOUT;
        const int bb = n0 / HW;
        const int p0 = n0 - bb * HW;
#pragma unroll
        for (int i = 0; i < 8; i++) {
            int m = m0 + ((i < 4) ? (tm * 4 + i) : (64 + tm * 4 + (i - 4)));
            float bvv = bias[m];
            float* rowp = Cdst + ((size_t)bb * M + m) * HW + p0;
#pragma unroll
            for (int jh = 0; jh < 2; jh++) {
                float4 r;
                r.x = acc[i][jh * 4 + 0] + bvv;
                r.y = acc[i][jh * 4 + 1] + bvv;
                r.z = acc[i][jh * 4 + 2] + bvv;
                r.w = acc[i][jh * 4 + 3] + bvv;
                if (RELU) {
                    r.x = fmaxf(r.x, 0.f); r.y = fmaxf(r.y, 0.f);
                    r.z = fmaxf(r.z, 0.f); r.w = fmaxf(r.w, 0.f);
                }
                *(float4*)(rowp + jh * 64 + tn * 4) = r;
            }
        }
    } else {
        float c2v[8];
#pragma unroll
        for (int i = 0; i < 8; i++) {
            int m = m0 + ((i < 4) ? (tm * 4 + i) : (64 + tm * 4 + (i - 4)));
            c2v[i] = bias[m];    // bias = g_c2h here
        }
        if (tid < 128) red[tid] = 0ULL;
        __syncthreads();
#pragma unroll
        for (int j = 0; j < 8; j++) {
            int nl = (j < 4) ? (tn * 4 + j) : (64 + tn * 4 + (j - 4));
            unsigned long long best = 0ULL;
#pragma unroll
            for (int i = 0; i < 8; i++) {
                int m = m0 + ((i < 4) ? (tm * 4 + i) : (64 + tm * 4 + (i - 4)));
                unsigned long long key = pack_key(acc[i][j] - c2v[i], m);
                best = (key > best) ? key : best;
            }
            atomicMax(&red[nl], best);
        }
        __syncthreads();
        if (tid < 128) atomicMax(&g_best[n0 + tid], red[tid]);
    }
}

// ---------------------------------------------------------------------------
// Finalize: decode tokens, write tokens (as float) + gathered embeddings.
// ---------------------------------------------------------------------------
__global__ __launch_bounds__(192) void output_kernel(
    const float* __restrict__ table, float* __restrict__ out)
{
    int p = blockIdx.x;
    unsigned long long key = g_best[p];
    unsigned v = 0xFFFFFFFFu - (unsigned)(key & 0xFFFFFFFFu);
    if (threadIdx.x == 0) out[p] = (float)v;
    float4* dst = (float4*)(out + 16384 + (size_t)p * 768);
    const float4* src = (const float4*)(table + (size_t)v * 768);
    dst[threadIdx.x] = src[threadIdx.x];   // 192 threads * float4 = 768 floats
}

// ---------------------------------------------------------------------------
extern "C" void kernel_launch(void* const* d_in, const int* in_sizes, int n_in,
                              void* d_out, int out_size)
{
    (void)in_sizes; (void)n_in; (void)out_size;
    const float* image = (const float*)d_in[0];
    const float* w1 = (const float*)d_in[1];
    const float* b1 = (const float*)d_in[2];
    const float* w2 = (const float*)d_in[3];
    const float* b2 = (const float*)d_in[4];
    const float* w3 = (const float*)d_in[5];
    const float* b3 = (const float*)d_in[6];
    const float* cb = (const float*)d_in[7];
    const float* tab = (const float*)d_in[8];
    float* out = (float*)d_out;

    float *p1, *p2, *p3, *pc2;
    cudaGetSymbolAddress((void**)&p1, g_f1);
    cudaGetSymbolAddress((void**)&p2, g_f2);
    cudaGetSymbolAddress((void**)&p3, g_f3);
    cudaGetSymbolAddress((void**)&pc2, g_c2h);

    c2half_kernel<<<1024, 256>>>(cb);
    init_best_kernel<<<64, 256>>>();
    conv1_kernel<<<512, 128>>>(image, w1, b1);

    // conv2: M=384, N=65536, K=1728, B gathered from g_f1
    gemm128_kernel<true, true, false, 192, 128, 128, 64, 64>
        <<<dim3(3, 512), 256>>>(w2, p1, b2, p2, 384, 65536, 1728);

    // conv3: M=768, N=16384, K=3456, B gathered from g_f2 (no relu)
    gemm128_kernel<true, false, false, 384, 64, 64, 32, 32>
        <<<dim3(6, 128), 256>>>(w3, p2, b3, p3, 768, 16384, 3456);

    // distance GEMM + fused argmax: M=8192, N=16384, K=768
    gemm128_kernel<false, false, true, 0, 0, 0, 1, 1>
        <<<dim3(64, 128), 256>>>(cb, p3, pc2, nullptr, 8192, 16384, 768);

    output_kernel<<<16384, 192>>>(tab, out);
}

// round 3
// speedup vs baseline: 1.8569x; 1.8569x over previous
#include <cuda_runtime.h>
#include <cuda_bf16.h>
#include <cstdint>

// ---------------------------------------------------------------------------
//   image [16,3,256,256] -> conv1 s2 relu -> g_f1 [16,192,128,128] (fp32 NCHW)
//   conv2 s2 relu (bf16x3 mma.sync) -> g_f2 [16,384,64,64] (fp32 NCHW)
//   conv3 s2      (bf16x3 mma.sync) -> g_f3 [16384 tokens][768] (token-major)
//   distance GEMM (bf16x3 mma.sync) + fused argmax -> g_best
//   output: [ tokens(16384 as f32) | embeddings(16384x768) ]
// NOTE: harness compiles PTX at compute_100 (no 'a') => tcgen05/TMEM illegal.
//       Legacy sm_80-class mma.sync + ldmatrix is the fastest legal path.
// ---------------------------------------------------------------------------

__device__ float g_f1[16u * 192u * 128u * 128u];
__device__ float g_f2[16u * 384u * 64u * 64u];
__device__ float g_f3[16384u * 768u];
__device__ float g_c2h[8192];
__device__ unsigned long long g_best[16384];

// ------------------------------ helpers -----------------------------------
__device__ __forceinline__ uint32_t smem_u32(const void* p) {
    uint32_t a;
    asm("{ .reg .u64 t; cvta.to.shared.u64 t, %1; cvt.u32.u64 %0, t; }"
        : "=r"(a) : "l"(p));
    return a;
}

__device__ __forceinline__ void ldsm4(uint32_t* r, uint32_t addr) {
    asm volatile("ldmatrix.sync.aligned.m8n8.x4.shared.b16 {%0,%1,%2,%3}, [%4];"
        : "=r"(r[0]), "=r"(r[1]), "=r"(r[2]), "=r"(r[3]) : "r"(addr));
}

__device__ __forceinline__ void mma_bf16(float* c, const uint32_t* a, const uint32_t* b) {
    asm volatile("mma.sync.aligned.m16n8k16.row.col.f32.bf16.bf16.f32 "
        "{%0,%1,%2,%3}, {%4,%5,%6,%7}, {%8,%9}, {%0,%1,%2,%3};"
        : "+f"(c[0]), "+f"(c[1]), "+f"(c[2]), "+f"(c[3])
        : "r"(a[0]), "r"(a[1]), "r"(a[2]), "r"(a[3]), "r"(b[0]), "r"(b[1]));
}

__device__ __forceinline__ unsigned long long pack_key(float s, int v) {
    unsigned u = __float_as_uint(s);
    u = (u & 0x80000000u) ? ~u : (u | 0x80000000u);
    return ((unsigned long long)u << 32) | (unsigned)(0xFFFFFFFFu - (unsigned)v);
}

// convert 8 fp32 -> bf16 hi/lo, store 16B each into 48B-strided tile rows
__device__ __forceinline__ void cvt_store(char* base_hi, char* base_lo,
                                          int row, int half, const float* v) {
    uint32_t h[4], l[4];
#pragma unroll
    for (int i = 0; i < 4; i++) {
        float v0 = v[2 * i], v1 = v[2 * i + 1];
        __nv_bfloat162 hp = __floats2bfloat162_rn(v0, v1);
        float r0 = v0 - __bfloat162float(hp.x);
        float r1 = v1 - __bfloat162float(hp.y);
        __nv_bfloat162 lp = __floats2bfloat162_rn(r0, r1);
        h[i] = *(uint32_t*)&hp;
        l[i] = *(uint32_t*)&lp;
    }
    int off = row * 48 + half * 16;
    *(uint4*)(base_hi + off) = make_uint4(h[0], h[1], h[2], h[3]);
    *(uint4*)(base_lo + off) = make_uint4(l[0], l[1], l[2], l[3]);
}

// ---------------------------------------------------------------------------
// bf16x3 mma GEMM. 128x128 tile, K-chunk 16, double-buffered smem.
//  MODE 0: conv2 (A=w2 direct ld=1728, B=gather f1, epi NCHW + bias + relu)
//  MODE 1: conv3 (A=gather f2 [tokens], B=w3 direct ld=3456, epi token-major + bias)
//  MODE 2: dist  (A=f3 direct ld=768,  B=codebook direct ld=768, epi argmax)
// Tile rows padded to 48B => ldmatrix conflict-free.
// ---------------------------------------------------------------------------
static constexpr int TILE = 128 * 48;       // 6144 B (hi or lo, A or B)
static constexpr int STAGE = 4 * TILE;      // 24576 B
static constexpr int GEMM_SMEM = 2 * STAGE + 512;

template<int MODE>
__global__ __launch_bounds__(256, 1) void mma_gemm(
    const float* __restrict__ Asrc, const float* __restrict__ Bsrc,
    const float* __restrict__ vec, float* __restrict__ Cdst, int K)
{
    extern __shared__ char sm[];
    const uint32_t sb = smem_u32(sm);
    const int tid = threadIdx.x, wid = tid >> 5, lane = tid & 31;
    const int m0 = blockIdx.x * 128, n0 = blockIdx.y * 128;
    const int NT = K >> 4;

    float* vecs = (float*)(sm + 2 * STAGE);
    if (tid < 128) vecs[tid] = vec[(MODE == 0 ? m0 : n0) + tid];

    const int lrow = tid >> 1, lhalf = tid & 1;

    // ---- per-thread source setup (fixed across k-chunks)
    const float* aptr = nullptr;   // direct A row ptr
    const float* bptr = nullptr;   // direct B row ptr
    const float* gbase = nullptr;  // gather base
    int giy0 = 0, gix0 = 0;

    if constexpr (MODE == 0) {
        aptr = Asrc + (size_t)(m0 + lrow) * 1728;
        int n = n0 + lrow;                       // spatial output index
        int bb = n >> 12, rem = n & 4095;        // HW = 64*64
        int oy = rem >> 6, ox = rem & 63;
        gbase = Bsrc + (size_t)bb * (192 * 128 * 128);
        giy0 = 2 * oy - 1; gix0 = 2 * ox - 1;
    } else if constexpr (MODE == 1) {
        int n = m0 + lrow;                       // token index
        int bb = n >> 10, rem = n & 1023;        // HW = 32*32
        int oy = rem >> 5, ox = rem & 31;
        gbase = Asrc + (size_t)bb * (384 * 64 * 64);
        giy0 = 2 * oy - 1; gix0 = 2 * ox - 1;
        bptr = Bsrc + (size_t)(n0 + lrow) * 3456;
    } else {
        aptr = Asrc + (size_t)(m0 + lrow) * 768;
        bptr = Bsrc + (size_t)(n0 + lrow) * 768;
    }

    float pa[8], pb[8];
    auto load_regs = [&](int kt) {
        const int k0 = kt * 16 + lhalf * 8;
        if constexpr (MODE == 0) {
            float4 v0 = *(const float4*)(aptr + k0);
            float4 v1 = *(const float4*)(aptr + k0 + 4);
            pa[0]=v0.x; pa[1]=v0.y; pa[2]=v0.z; pa[3]=v0.w;
            pa[4]=v1.x; pa[5]=v1.y; pa[6]=v1.z; pa[7]=v1.w;
#pragma unroll
            for (int j = 0; j < 8; j++) {
                int k = k0 + j;
                int ci = (k * 7282) >> 16;         // k/9
                int r = k - ci * 9;
                int ky = (r * 11) >> 5;            // r/3
                int kx = r - ky * 3;
                int iy = giy0 + ky, ix = gix0 + kx;
                bool ok = (iy >= 0) && (iy < 128) && (ix >= 0) && (ix < 128);
                pb[j] = ok ? gbase[(size_t)((ci * 128 + iy) * 128 + ix)] : 0.f;
            }
        } else if constexpr (MODE == 1) {
#pragma unroll
            for (int j = 0; j < 8; j++) {
                int k = k0 + j;
                int ci = (k * 7282) >> 16;
                int r = k - ci * 9;
                int ky = (r * 11) >> 5;
                int kx = r - ky * 3;
                int iy = giy0 + ky, ix = gix0 + kx;
                bool ok = (iy >= 0) && (iy < 64) && (ix >= 0) && (ix < 64);
                pa[j] = ok ? gbase[(size_t)((ci * 64 + iy) * 64 + ix)] : 0.f;
            }
            float4 v0 = *(const float4*)(bptr + k0);
            float4 v1 = *(const float4*)(bptr + k0 + 4);
            pb[0]=v0.x; pb[1]=v0.y; pb[2]=v0.z; pb[3]=v0.w;
            pb[4]=v1.x; pb[5]=v1.y; pb[6]=v1.z; pb[7]=v1.w;
        } else {
            float4 v0 = *(const float4*)(aptr + k0);
            float4 v1 = *(const float4*)(aptr + k0 + 4);
            pa[0]=v0.x; pa[1]=v0.y; pa[2]=v0.z; pa[3]=v0.w;
            pa[4]=v1.x; pa[5]=v1.y; pa[6]=v1.z; pa[7]=v1.w;
            float4 w0 = *(const float4*)(bptr + k0);
            float4 w1 = *(const float4*)(bptr + k0 + 4);
            pb[0]=w0.x; pb[1]=w0.y; pb[2]=w0.z; pb[3]=w0.w;
            pb[4]=w1.x; pb[5]=w1.y; pb[6]=w1.z; pb[7]=w1.w;
        }
    };

    auto store_stage = [&](int s) {
        char* st = sm + s * STAGE;
        cvt_store(st,            st + TILE,     lrow, lhalf, pa);   // A hi/lo
        cvt_store(st + 2 * TILE, st + 3 * TILE, lrow, lhalf, pb);   // B hi/lo
    };

    // ---- warp tiling: 2 (m) x 4 (n), each warp 64x32
    const int wm = wid & 1, wn = wid >> 1;
    const int q = lane >> 3, rr = lane & 7;
    const uint32_t a_off = (uint32_t)((wm * 64 + (q & 1) * 8 + rr) * 48 + (q >> 1) * 16);
    const uint32_t b_off = (uint32_t)(((q >> 1) * 8 + rr) * 48 + (q & 1) * 16);

    float acc[4][4][4];
#pragma unroll
    for (int i = 0; i < 4; i++)
#pragma unroll
        for (int j = 0; j < 4; j++)
#pragma unroll
            for (int e = 0; e < 4; e++) acc[i][j][e] = 0.f;

    load_regs(0);
    store_stage(0);
    __syncthreads();

    for (int kt = 0; kt < NT; kt++) {
        const int s = kt & 1;
        if (kt + 1 < NT) load_regs(kt + 1);

        const uint32_t Ah_b = sb + s * STAGE;
        const uint32_t Al_b = Ah_b + TILE;
        const uint32_t Bh_b = Ah_b + 2 * TILE;
        const uint32_t Bl_b = Ah_b + 3 * TILE;

        uint32_t Ah[4][4], Al[4][4], Bh[2][4], Bl[2][4];
#pragma unroll
        for (int mi = 0; mi < 4; mi++) {
            ldsm4(Ah[mi], Ah_b + a_off + mi * 16 * 48);
            ldsm4(Al[mi], Al_b + a_off + mi * 16 * 48);
        }
#pragma unroll
        for (int nq = 0; nq < 2; nq++) {
            uint32_t roff = b_off + (uint32_t)((wn * 32 + nq * 16) * 48);
            ldsm4(Bh[nq], Bh_b + roff);
            ldsm4(Bl[nq], Bl_b + roff);
        }
#pragma unroll
        for (int mi = 0; mi < 4; mi++)
#pragma unroll
            for (int nj = 0; nj < 4; nj++) {
                const uint32_t* bh = &Bh[nj >> 1][(nj & 1) * 2];
                const uint32_t* bl = &Bl[nj >> 1][(nj & 1) * 2];
                mma_bf16(acc[mi][nj], Ah[mi], bh);   // hi*hi
                mma_bf16(acc[mi][nj], Ah[mi], bl);   // hi*lo
                mma_bf16(acc[mi][nj], Al[mi], bh);   // lo*hi
            }

        if (kt + 1 < NT) {
            store_stage(s ^ 1);
            __syncthreads();
        }
    }

    // ---- epilogue. Fragment c[e]: rows tg(+8), cols 2*tp + e%2
    const int tg = lane >> 2, tp = lane & 3;
    const int mbase = m0 + wm * 64;
    const int nbase_l = wn * 32;            // local n within tile

    if constexpr (MODE == 0) {
        const int bb = n0 >> 12;
        const int sp0 = (n0 & 4095) + nbase_l;
#pragma unroll
        for (int mi = 0; mi < 4; mi++)
#pragma unroll
            for (int h = 0; h < 2; h++) {
                int ml = wm * 64 + mi * 16 + tg + h * 8;
                int m = m0 + mi * 16 + tg + h * 8 + wm * 64;
                float bv = vecs[ml];
                float* rowp = Cdst + ((size_t)bb * 384 + m) * 4096;
#pragma unroll
                for (int nj = 0; nj < 4; nj++) {
                    float2 o;
                    o.x = fmaxf(acc[mi][nj][h * 2 + 0] + bv, 0.f);
                    o.y = fmaxf(acc[mi][nj][h * 2 + 1] + bv, 0.f);
                    *(float2*)(rowp + sp0 + nj * 8 + 2 * tp) = o;
                }
            }
    } else if constexpr (MODE == 1) {
#pragma unroll
        for (int mi = 0; mi < 4; mi++)
#pragma unroll
            for (int h = 0; h < 2; h++) {
                int m = mbase + mi * 16 + tg + h * 8;     // token
                float* rowp = Cdst + (size_t)m * 768 + n0;
#pragma unroll
                for (int nj = 0; nj < 4; nj++) {
                    int nl = nbase_l + nj * 8 + 2 * tp;
                    float2 o;
                    o.x = acc[mi][nj][h * 2 + 0] + vecs[nl + 0];
                    o.y = acc[mi][nj][h * 2 + 1] + vecs[nl + 1];
                    *(float2*)(rowp + nl) = o;
                }
            }
    } else {
#pragma unroll
        for (int mi = 0; mi < 4; mi++)
#pragma unroll
            for (int h = 0; h < 2; h++) {
                int m = mbase + mi * 16 + tg + h * 8;     // token
                unsigned long long best = 0ull;
#pragma unroll
                for (int nj = 0; nj < 4; nj++)
#pragma unroll
                    for (int e = 0; e < 2; e++) {
                        int nl = nbase_l + nj * 8 + 2 * tp + e;
                        float sscore = acc[mi][nj][h * 2 + e] - vecs[nl];
                        unsigned long long key = pack_key(sscore, n0 + nl);
                        best = key > best ? key : best;
                    }
                unsigned long long o1 = __shfl_xor_sync(0xFFFFFFFFu, best, 1);
                best = best > o1 ? best : o1;
                unsigned long long o2 = __shfl_xor_sync(0xFFFFFFFFu, best, 2);
                best = best > o2 ? best : o2;
                if (tp == 0) atomicMax(&g_best[m], best);
            }
    }
}

// ---------------------------------------------------------------------------
// conv1: Cin=3, 3x3 s2 pad1, relu (fp32 SIMT, proven in R1)
// ---------------------------------------------------------------------------
__global__ __launch_bounds__(128) void conv1_kernel(
    const float* __restrict__ in, const float* __restrict__ w,
    const float* __restrict__ bias)
{
    __shared__ float Ws[192 * 27];
    __shared__ float Bsm[192];
    for (int i = threadIdx.x; i < 192 * 27; i += 128) Ws[i] = w[i];
    for (int i = threadIdx.x; i < 192; i += 128) Bsm[i] = bias[i];
    __syncthreads();

    int g = blockIdx.x * 128 + threadIdx.x;
    int x0 = (g & 31) * 4;
    int y = (g >> 5) & 127;
    int b = g >> 12;

    float xv[3][3][9];
    int iy0 = 2 * y - 1;
    int ix0 = 2 * x0 - 1;
#pragma unroll
    for (int ci = 0; ci < 3; ci++)
#pragma unroll
        for (int ky = 0; ky < 3; ky++) {
            int iy = iy0 + ky;
            bool yok = (iy >= 0) && (iy < 256);
            const float* rowp = in + (((size_t)b * 3 + ci) * 256 + iy) * 256;
#pragma unroll
            for (int c = 0; c < 9; c++) {
                int ix = ix0 + c;
                xv[ci][ky][c] = (yok && ix >= 0 && ix < 256) ? rowp[ix] : 0.f;
            }
        }

    float* outp = g_f1 + (size_t)b * 192 * 16384 + y * 128 + x0;
    for (int co = 0; co < 192; co++) {
        float bv = Bsm[co];
        float a0 = bv, a1 = bv, a2 = bv, a3 = bv;
        const float* wp = &Ws[co * 27];
#pragma unroll
        for (int ci = 0; ci < 3; ci++)
#pragma unroll
            for (int ky = 0; ky < 3; ky++)
#pragma unroll
                for (int kx = 0; kx < 3; kx++) {
                    float wv = wp[ci * 9 + ky * 3 + kx];
                    a0 = fmaf(wv, xv[ci][ky][0 + kx], a0);
                    a1 = fmaf(wv, xv[ci][ky][2 + kx], a1);
                    a2 = fmaf(wv, xv[ci][ky][4 + kx], a2);
                    a3 = fmaf(wv, xv[ci][ky][6 + kx], a3);
                }
        float4 r;
        r.x = fmaxf(a0, 0.f); r.y = fmaxf(a1, 0.f);
        r.z = fmaxf(a2, 0.f); r.w = fmaxf(a3, 0.f);
        *(float4*)(outp + (size_t)co * 16384) = r;
    }
}

// ---------------------------------------------------------------------------
__global__ void c2half_kernel(const float* __restrict__ cb) {
    int v = blockIdx.x * 8 + (threadIdx.x >> 5);
    int lane = threadIdx.x & 31;
    const float* row = cb + (size_t)v * 768;
    float s = 0.f;
    for (int c = lane; c < 768; c += 32) { float t = row[c]; s = fmaf(t, t, s); }
#pragma unroll
    for (int o = 16; o > 0; o >>= 1) s += __shfl_xor_sync(0xFFFFFFFFu, s, o);
    if (lane == 0) g_c2h[v] = 0.5f * s;
}

__global__ void init_best_kernel() {
    int i = blockIdx.x * 256 + threadIdx.x;
    if (i < 16384) g_best[i] = 0ULL;
}

__global__ __launch_bounds__(192) void output_kernel(
    const float* __restrict__ table, float* __restrict__ out)
{
    int p = blockIdx.x;
    unsigned long long key = g_best[p];
    unsigned v = 0xFFFFFFFFu - (unsigned)(key & 0xFFFFFFFFu);
    if (threadIdx.x == 0) out[p] = (float)v;
    float4* dst = (float4*)(out + 16384 + (size_t)p * 768);
    const float4* src = (const float4*)(table + (size_t)v * 768);
    dst[threadIdx.x] = src[threadIdx.x];
}

// ---------------------------------------------------------------------------
extern "C" void kernel_launch(void* const* d_in, const int* in_sizes, int n_in,
                              void* d_out, int out_size)
{
    (void)in_sizes; (void)n_in; (void)out_size;
    const float* image = (const float*)d_in[0];
    const float* w1 = (const float*)d_in[1];
    const float* b1 = (const float*)d_in[2];
    const float* w2 = (const float*)d_in[3];
    const float* b2 = (const float*)d_in[4];
    const float* w3 = (const float*)d_in[5];
    const float* b3 = (const float*)d_in[6];
    const float* cb = (const float*)d_in[7];
    const float* tab = (const float*)d_in[8];
    float* out = (float*)d_out;

    float *p1, *p2, *p3, *pc2;
    cudaGetSymbolAddress((void**)&p1, g_f1);
    cudaGetSymbolAddress((void**)&p2, g_f2);
    cudaGetSymbolAddress((void**)&p3, g_f3);
    cudaGetSymbolAddress((void**)&pc2, g_c2h);

    cudaFuncSetAttribute(mma_gemm<0>, cudaFuncAttributeMaxDynamicSharedMemorySize, GEMM_SMEM);
    cudaFuncSetAttribute(mma_gemm<1>, cudaFuncAttributeMaxDynamicSharedMemorySize, GEMM_SMEM);
    cudaFuncSetAttribute(mma_gemm<2>, cudaFuncAttributeMaxDynamicSharedMemorySize, GEMM_SMEM);

    c2half_kernel<<<1024, 256>>>(cb);
    init_best_kernel<<<64, 256>>>();
    conv1_kernel<<<512, 128>>>(image, w1, b1);

    // conv2: M=384 (w2 rows), N=65536 (spatial), K=1728
    mma_gemm<0><<<dim3(3, 512), 256, GEMM_SMEM>>>(w2, p1, b2, p2, 1728);
    // conv3: M=16384 (tokens, gathered), N=768 (w3 rows), K=3456
    mma_gemm<1><<<dim3(128, 6), 256, GEMM_SMEM>>>(p2, w3, b3, p3, 3456);
    // distance: M=16384 (tokens), N=8192 (codes), K=768, fused argmax
    mma_gemm<2><<<dim3(128, 64), 256, GEMM_SMEM>>>(p3, cb, pc2, nullptr, 768);

    output_kernel<<<16384, 192>>>(tab, out);
}

// round 4
// speedup vs baseline: 2.2721x; 1.2236x over previous
#include <cuda_runtime.h>
#include <cuda_bf16.h>
#include <cstdint>

// ---------------------------------------------------------------------------
//   image [16,3,256,256] -> conv1 s2 relu -> g_f1i [16,192,128,128] {hi,lo} u32
//   conv2 s2 relu (bf16x3 mma) -> g_f2i [16,384,64,64] {hi,lo} u32
//   conv3 s2      (bf16x3 mma) -> g_f3h/g_f3l [16384][768] bf16 planes
//   distance GEMM (bf16x3 mma) + fused argmax -> g_best
//   weights/codebook pre-split to bf16 hi/lo planes.
//   All GEMM operands are bf16 in HBM: main loop = cp.async/LDG + ldsm + mma.
// ---------------------------------------------------------------------------

__device__ uint32_t g_f1i[16u * 192u * 128u * 128u];
__device__ uint32_t g_f2i[16u * 384u * 64u * 64u];
__device__ __nv_bfloat16 g_f3h[16384u * 768u];
__device__ __nv_bfloat16 g_f3l[16384u * 768u];
__device__ __nv_bfloat16 g_w2h[384u * 1728u];
__device__ __nv_bfloat16 g_w2l[384u * 1728u];
__device__ __nv_bfloat16 g_w3h[768u * 3456u];
__device__ __nv_bfloat16 g_w3l[768u * 3456u];
__device__ __nv_bfloat16 g_cbh[8192u * 768u];
__device__ __nv_bfloat16 g_cbl[8192u * 768u];
__device__ float g_c2h[8192];
__device__ unsigned long long g_best[16384];

// ------------------------------ helpers -----------------------------------
__device__ __forceinline__ uint32_t smem_u32(const void* p) {
    uint32_t a;
    asm("{ .reg .u64 t; cvta.to.shared.u64 t, %1; cvt.u32.u64 %0, t; }"
        : "=r"(a) : "l"(p));
    return a;
}
__device__ __forceinline__ void ldsm4(uint32_t* r, uint32_t addr) {
    asm volatile("ldmatrix.sync.aligned.m8n8.x4.shared.b16 {%0,%1,%2,%3}, [%4];"
        : "=r"(r[0]), "=r"(r[1]), "=r"(r[2]), "=r"(r[3]) : "r"(addr));
}
__device__ __forceinline__ void mma_bf16(float* c, const uint32_t* a, const uint32_t* b) {
    asm volatile("mma.sync.aligned.m16n8k16.row.col.f32.bf16.bf16.f32 "
        "{%0,%1,%2,%3}, {%4,%5,%6,%7}, {%8,%9}, {%0,%1,%2,%3};"
        : "+f"(c[0]), "+f"(c[1]), "+f"(c[2]), "+f"(c[3])
        : "r"(a[0]), "r"(a[1]), "r"(a[2]), "r"(a[3]), "r"(b[0]), "r"(b[1]));
}
__device__ __forceinline__ uint32_t prmt(uint32_t a, uint32_t b, uint32_t c) {
    uint32_t d;
    asm("prmt.b32 %0, %1, %2, %3;" : "=r"(d) : "r"(a), "r"(b), "r"(c));
    return d;
}
__device__ __forceinline__ void cp16(uint32_t dst, const void* src) {
    asm volatile("cp.async.cg.shared.global [%0], [%1], 16;"
                 :: "r"(dst), "l"(src) : "memory");
}
__device__ __forceinline__ void sts128(uint32_t addr, uint32_t a, uint32_t b,
                                       uint32_t c, uint32_t d) {
    asm volatile("st.shared.v4.b32 [%0], {%1,%2,%3,%4};"
                 :: "r"(addr), "r"(a), "r"(b), "r"(c), "r"(d) : "memory");
}
__device__ __forceinline__ unsigned long long pack_key(float s, int v) {
    unsigned u = __float_as_uint(s);
    u = (u & 0x80000000u) ? ~u : (u | 0x80000000u);
    return ((unsigned long long)u << 32) | (unsigned)(0xFFFFFFFFu - (unsigned)v);
}
// pack fp32 -> {hi bf16 in [15:0], lo bf16 in [31:16]}
__device__ __forceinline__ uint32_t pack_hl(float v) {
    __nv_bfloat16 h = __float2bfloat16(v);
    float hf = __bfloat162float(h);
    __nv_bfloat16 l = __float2bfloat16(v - hf);
    return ((uint32_t)__bfloat16_as_ushort(l) << 16) | __bfloat16_as_ushort(h);
}

// ---------------------------------------------------------------------------
// bf16x3 mma GEMM. 128x128 tile, K-chunk 16, 3-stage cp.async pipeline.
//  MODE 0: conv2  A=w2 planes (direct), B=gather f1i, out f2i {hi,lo}+bias+relu
//  MODE 1: conv3  A=gather f2i,  B=w3 planes (direct), out f3 planes + bias
//  MODE 2: dist   A=f3 planes,   B=cb planes (direct), fused argmax
// Tile row stride 48B -> ldmatrix conflict-free.
// ---------------------------------------------------------------------------
static constexpr int TILE = 128 * 48;      // 6144 B
static constexpr int STAGE = 4 * TILE;     // Ah,Al,Bh,Bl = 24576 B
static constexpr int GEMM_SMEM = 3 * STAGE + 512;

template<int MODE>
__global__ __launch_bounds__(256, 2) void mma_gemm(
    const void* __restrict__ pa0, const void* __restrict__ pa1,
    const void* __restrict__ pb0, const void* __restrict__ pb1,
    const float* __restrict__ vec, void* __restrict__ o0,
    void* __restrict__ o1, int K)
{
    extern __shared__ char sm[];
    const uint32_t sb = smem_u32(sm);
    const int tid = threadIdx.x, wid = tid >> 5, lane = tid & 31;
    const int m0 = blockIdx.x * 128, n0 = blockIdx.y * 128;
    const int NT = K >> 4;

    float* vecs = (float*)(sm + 3 * STAGE);
    if (tid < 128) vecs[tid] = vec[(MODE == 0 ? m0 : n0) + tid];

    const int lrow = tid >> 1, lhalf = tid & 1;

    // ---- source setup
    const char* dirA_h = nullptr; const char* dirA_l = nullptr;
    const char* dirB_h = nullptr; const char* dirB_l = nullptr;
    const uint32_t* gsrc = nullptr;
    int giy0 = 0, gix0 = 0;

    if constexpr (MODE == 0) {
        dirA_h = (const char*)pa0 + ((size_t)(m0 + lrow) * 1728 + lhalf * 8) * 2;
        dirA_l = (const char*)pa1 + ((size_t)(m0 + lrow) * 1728 + lhalf * 8) * 2;
        int n = n0 + lrow;
        int bb = n >> 12, rem = n & 4095;
        int oy = rem >> 6, ox = rem & 63;
        gsrc = (const uint32_t*)pb0 + (size_t)bb * (192u * 128u * 128u);
        giy0 = 2 * oy - 1; gix0 = 2 * ox - 1;
    } else if constexpr (MODE == 1) {
        int n = m0 + lrow;
        int bb = n >> 10, rem = n & 1023;
        int oy = rem >> 5, ox = rem & 31;
        gsrc = (const uint32_t*)pa0 + (size_t)bb * (384u * 64u * 64u);
        giy0 = 2 * oy - 1; gix0 = 2 * ox - 1;
        dirB_h = (const char*)pb0 + ((size_t)(n0 + lrow) * 3456 + lhalf * 8) * 2;
        dirB_l = (const char*)pb1 + ((size_t)(n0 + lrow) * 3456 + lhalf * 8) * 2;
    } else {
        dirA_h = (const char*)pa0 + ((size_t)(m0 + lrow) * 768 + lhalf * 8) * 2;
        dirA_l = (const char*)pa1 + ((size_t)(m0 + lrow) * 768 + lhalf * 8) * 2;
        dirB_h = (const char*)pb0 + ((size_t)(n0 + lrow) * 768 + lhalf * 8) * 2;
        dirB_l = (const char*)pb1 + ((size_t)(n0 + lrow) * 768 + lhalf * 8) * 2;
    }

    const uint32_t loff = (uint32_t)(lrow * 48 + lhalf * 16);

    auto gather8 = [&](int kt, uint32_t dhi, uint32_t dlo, int HIN, int WIN) {
        uint32_t e[8];
        const int k0 = kt * 16 + lhalf * 8;
#pragma unroll
        for (int j = 0; j < 8; j++) {
            int k = k0 + j;
            int ci = (k * 7282) >> 16;     // k/9
            int r = k - ci * 9;
            int ky = (r * 11) >> 5;        // r/3
            int kx = r - ky * 3;
            int iy = giy0 + ky, ix = gix0 + kx;
            bool ok = (iy >= 0) && (iy < HIN) && (ix >= 0) && (ix < WIN);
            e[j] = ok ? gsrc[(size_t)((ci * HIN + iy) * WIN + ix)] : 0u;
        }
        sts128(dhi, prmt(e[0], e[1], 0x5410), prmt(e[2], e[3], 0x5410),
                    prmt(e[4], e[5], 0x5410), prmt(e[6], e[7], 0x5410));
        sts128(dlo, prmt(e[0], e[1], 0x7632), prmt(e[2], e[3], 0x7632),
                    prmt(e[4], e[5], 0x7632), prmt(e[6], e[7], 0x7632));
    };

    auto load_chunk = [&](int kt, int s) {
        const uint32_t st = sb + s * STAGE + loff;
        if constexpr (MODE == 0) {
            cp16(st,            dirA_h + kt * 32);
            cp16(st + TILE,     dirA_l + kt * 32);
            gather8(kt, st + 2 * TILE, st + 3 * TILE, 128, 128);
        } else if constexpr (MODE == 1) {
            gather8(kt, st, st + TILE, 64, 64);
            cp16(st + 2 * TILE, dirB_h + kt * 32);
            cp16(st + 3 * TILE, dirB_l + kt * 32);
        } else {
            cp16(st,            dirA_h + kt * 32);
            cp16(st + TILE,     dirA_l + kt * 32);
            cp16(st + 2 * TILE, dirB_h + kt * 32);
            cp16(st + 3 * TILE, dirB_l + kt * 32);
        }
        asm volatile("cp.async.commit_group;" ::: "memory");
    };

    // ---- warp tiling: 2 (m) x 4 (n), each warp 64x32
    const int wm = wid & 1, wn = wid >> 1;
    const int q = lane >> 3, rr = lane & 7;
    const uint32_t a_off = (uint32_t)((wm * 64 + (q & 1) * 8 + rr) * 48 + (q >> 1) * 16);
    const uint32_t b_off = (uint32_t)(((q >> 1) * 8 + rr) * 48 + (q & 1) * 16);

    float acc[4][4][4];
#pragma unroll
    for (int i = 0; i < 4; i++)
#pragma unroll
        for (int j = 0; j < 4; j++)
#pragma unroll
            for (int e = 0; e < 4; e++) acc[i][j][e] = 0.f;

    load_chunk(0, 0);
    load_chunk(1, 1);

    int s = 0, sl = 2;
    for (int kt = 0; kt < NT; kt++) {
        if (kt + 1 < NT)
            asm volatile("cp.async.wait_group 1;" ::: "memory");
        else
            asm volatile("cp.async.wait_group 0;" ::: "memory");
        __syncthreads();

        const uint32_t Ah_b = sb + s * STAGE;
        const uint32_t Al_b = Ah_b + TILE;
        const uint32_t Bh_b = Ah_b + 2 * TILE;
        const uint32_t Bl_b = Ah_b + 3 * TILE;

        uint32_t Bh[2][4], Bl[2][4];
        ldsm4(Bh[0], Bh_b + b_off + (wn * 32) * 48);
        ldsm4(Bh[1], Bh_b + b_off + (wn * 32 + 16) * 48);
        ldsm4(Bl[0], Bl_b + b_off + (wn * 32) * 48);
        ldsm4(Bl[1], Bl_b + b_off + (wn * 32 + 16) * 48);
#pragma unroll
        for (int mi = 0; mi < 4; mi++) {
            uint32_t Ah[4], Al[4];
            ldsm4(Ah, Ah_b + a_off + mi * 16 * 48);
            ldsm4(Al, Al_b + a_off + mi * 16 * 48);
#pragma unroll
            for (int nj = 0; nj < 4; nj++) {
                const uint32_t* bh = &Bh[nj >> 1][(nj & 1) * 2];
                const uint32_t* bl = &Bl[nj >> 1][(nj & 1) * 2];
                mma_bf16(acc[mi][nj], Ah, bh);   // hi*hi
                mma_bf16(acc[mi][nj], Ah, bl);   // hi*lo
                mma_bf16(acc[mi][nj], Al, bh);   // lo*hi
            }
        }

        if (kt + 2 < NT) {
            load_chunk(kt + 2, sl);
            sl = (sl == 2) ? 0 : sl + 1;
        }
        s = (s == 2) ? 0 : s + 1;
    }

    // ---- epilogue. Fragment c[e]: rows tg(+8), cols 2*tp + e%2
    const int tg = lane >> 2, tp = lane & 3;

    if constexpr (MODE == 0) {
        uint32_t* Ci = (uint32_t*)o0;
        const int bb = n0 >> 12;
        const int sp0 = (n0 & 4095) + wn * 32;
#pragma unroll
        for (int mi = 0; mi < 4; mi++)
#pragma unroll
            for (int h = 0; h < 2; h++) {
                int ml = wm * 64 + mi * 16 + tg + h * 8;
                int m = m0 + ml;
                float bv = vecs[ml];
                uint32_t* rowp = Ci + ((size_t)bb * 384 + m) * 4096;
#pragma unroll
                for (int nj = 0; nj < 4; nj++) {
                    float v0 = fmaxf(acc[mi][nj][h * 2 + 0] + bv, 0.f);
                    float v1 = fmaxf(acc[mi][nj][h * 2 + 1] + bv, 0.f);
                    *(uint2*)(rowp + sp0 + nj * 8 + 2 * tp) =
                        make_uint2(pack_hl(v0), pack_hl(v1));
                }
            }
    } else if constexpr (MODE == 1) {
        __nv_bfloat16* fh = (__nv_bfloat16*)o0;
        __nv_bfloat16* fl = (__nv_bfloat16*)o1;
#pragma unroll
        for (int mi = 0; mi < 4; mi++)
#pragma unroll
            for (int h = 0; h < 2; h++) {
                int m = m0 + wm * 64 + mi * 16 + tg + h * 8;   // token
                __nv_bfloat16* rowh = fh + (size_t)m * 768 + n0;
                __nv_bfloat16* rowl = fl + (size_t)m * 768 + n0;
#pragma unroll
                for (int nj = 0; nj < 4; nj++) {
                    int nl = wn * 32 + nj * 8 + 2 * tp;
                    float v0 = acc[mi][nj][h * 2 + 0] + vecs[nl + 0];
                    float v1 = acc[mi][nj][h * 2 + 1] + vecs[nl + 1];
                    __nv_bfloat16 h0 = __float2bfloat16(v0);
                    __nv_bfloat16 h1 = __float2bfloat16(v1);
                    __nv_bfloat16 l0 = __float2bfloat16(v0 - __bfloat162float(h0));
                    __nv_bfloat16 l1 = __float2bfloat16(v1 - __bfloat162float(h1));
                    *(__nv_bfloat162*)(rowh + nl) = __nv_bfloat162(h0, h1);
                    *(__nv_bfloat162*)(rowl + nl) = __nv_bfloat162(l0, l1);
                }
            }
    } else {
#pragma unroll
        for (int mi = 0; mi < 4; mi++)
#pragma unroll
            for (int h = 0; h < 2; h++) {
                int m = m0 + wm * 64 + mi * 16 + tg + h * 8;   // token
                unsigned long long best = 0ull;
#pragma unroll
                for (int nj = 0; nj < 4; nj++)
#pragma unroll
                    for (int e = 0; e < 2; e++) {
                        int nl = wn * 32 + nj * 8 + 2 * tp + e;
                        float sc = acc[mi][nj][h * 2 + e] - vecs[nl];
                        unsigned long long key = pack_key(sc, n0 + nl);
                        best = key > best ? key : best;
                    }
                unsigned long long o = __shfl_xor_sync(0xFFFFFFFFu, best, 1);
                best = best > o ? best : o;
                o = __shfl_xor_sync(0xFFFFFFFFu, best, 2);
                best = best > o ? best : o;
                if (tp == 0) atomicMax(&g_best[m], best);
            }
    }
}

// ---------------------------------------------------------------------------
// conv1: Cin=3, 3x3 s2 pad1, relu -> interleaved {hi,lo} uint32 NCHW
// ---------------------------------------------------------------------------
__global__ __launch_bounds__(128) void conv1_kernel(
    const float* __restrict__ in, const float* __restrict__ w,
    const float* __restrict__ bias)
{
    __shared__ float Ws[192 * 27];
    __shared__ float Bsm[192];
    for (int i = threadIdx.x; i < 192 * 27; i += 128) Ws[i] = w[i];
    for (int i = threadIdx.x; i < 192; i += 128) Bsm[i] = bias[i];
    __syncthreads();

    int g = blockIdx.x * 128 + threadIdx.x;
    int x0 = (g & 31) * 4;
    int y = (g >> 5) & 127;
    int b = g >> 12;

    float xv[3][3][9];
    int iy0 = 2 * y - 1;
    int ix0 = 2 * x0 - 1;
#pragma unroll
    for (int ci = 0; ci < 3; ci++)
#pragma unroll
        for (int ky = 0; ky < 3; ky++) {
            int iy = iy0 + ky;
            bool yok = (iy >= 0) && (iy < 256);
            const float* rowp = in + (((size_t)b * 3 + ci) * 256 + iy) * 256;
#pragma unroll
            for (int c = 0; c < 9; c++) {
                int ix = ix0 + c;
                xv[ci][ky][c] = (yok && ix >= 0 && ix < 256) ? rowp[ix] : 0.f;
            }
        }

    uint32_t* outp = g_f1i + (size_t)b * 192 * 16384 + y * 128 + x0;
    for (int co = 0; co < 192; co++) {
        float bv = Bsm[co];
        float a0 = bv, a1 = bv, a2 = bv, a3 = bv;
        const float* wp = &Ws[co * 27];
#pragma unroll
        for (int ci = 0; ci < 3; ci++)
#pragma unroll
            for (int ky = 0; ky < 3; ky++)
#pragma unroll
                for (int kx = 0; kx < 3; kx++) {
                    float wv = wp[ci * 9 + ky * 3 + kx];
                    a0 = fmaf(wv, xv[ci][ky][0 + kx], a0);
                    a1 = fmaf(wv, xv[ci][ky][2 + kx], a1);
                    a2 = fmaf(wv, xv[ci][ky][4 + kx], a2);
                    a3 = fmaf(wv, xv[ci][ky][6 + kx], a3);
                }
        uint4 r;
        r.x = pack_hl(fmaxf(a0, 0.f));
        r.y = pack_hl(fmaxf(a1, 0.f));
        r.z = pack_hl(fmaxf(a2, 0.f));
        r.w = pack_hl(fmaxf(a3, 0.f));
        *(uint4*)(outp + (size_t)co * 16384) = r;
    }
}

// ---------------------------------------------------------------------------
__global__ void cvt_planes_kernel(const float* __restrict__ src,
                                  __nv_bfloat16* __restrict__ hi,
                                  __nv_bfloat16* __restrict__ lo, int n)
{
    int i = blockIdx.x * 256 + threadIdx.x;
    if (i >= n) return;
    float v = src[i];
    __nv_bfloat16 h = __float2bfloat16(v);
    hi[i] = h;
    lo[i] = __float2bfloat16(v - __bfloat162float(h));
}

__global__ void c2half_kernel(const float* __restrict__ cb) {
    int v = blockIdx.x * 8 + (threadIdx.x >> 5);
    int lane = threadIdx.x & 31;
    const float* row = cb + (size_t)v * 768;
    float s = 0.f;
    for (int c = lane; c < 768; c += 32) { float t = row[c]; s = fmaf(t, t, s); }
#pragma unroll
    for (int o = 16; o > 0; o >>= 1) s += __shfl_xor_sync(0xFFFFFFFFu, s, o);
    if (lane == 0) g_c2h[v] = 0.5f * s;
}

__global__ void init_best_kernel() {
    int i = blockIdx.x * 256 + threadIdx.x;
    if (i < 16384) g_best[i] = 0ULL;
}

__global__ __launch_bounds__(192) void output_kernel(
    const float* __restrict__ table, float* __restrict__ out)
{
    int p = blockIdx.x;
    unsigned long long key = g_best[p];
    unsigned v = 0xFFFFFFFFu - (unsigned)(key & 0xFFFFFFFFu);
    if (threadIdx.x == 0) out[p] = (float)v;
    float4* dst = (float4*)(out + 16384 + (size_t)p * 768);
    const float4* src = (const float4*)(table + (size_t)v * 768);
    dst[threadIdx.x] = src[threadIdx.x];
}

// ---------------------------------------------------------------------------
extern "C" void kernel_launch(void* const* d_in, const int* in_sizes, int n_in,
                              void* d_out, int out_size)
{
    (void)in_sizes; (void)n_in; (void)out_size;
    const float* image = (const float*)d_in[0];
    const float* w1 = (const float*)d_in[1];
    const float* b1 = (const float*)d_in[2];
    const float* w2 = (const float*)d_in[3];
    const float* b2 = (const float*)d_in[4];
    const float* w3 = (const float*)d_in[5];
    const float* b3 = (const float*)d_in[6];
    const float* cb = (const float*)d_in[7];
    const float* tab = (const float*)d_in[8];
    float* out = (float*)d_out;

    void *pf1, *pf2, *pf3h, *pf3l, *pw2h, *pw2l, *pw3h, *pw3l, *pcbh, *pcbl, *pc2;
    cudaGetSymbolAddress(&pf1, g_f1i);
    cudaGetSymbolAddress(&pf2, g_f2i);
    cudaGetSymbolAddress(&pf3h, g_f3h);
    cudaGetSymbolAddress(&pf3l, g_f3l);
    cudaGetSymbolAddress(&pw2h, g_w2h);
    cudaGetSymbolAddress(&pw2l, g_w2l);
    cudaGetSymbolAddress(&pw3h, g_w3h);
    cudaGetSymbolAddress(&pw3l, g_w3l);
    cudaGetSymbolAddress(&pcbh, g_cbh);
    cudaGetSymbolAddress(&pcbl, g_cbl);
    cudaGetSymbolAddress(&pc2, g_c2h);

    cudaFuncSetAttribute(mma_gemm<0>, cudaFuncAttributeMaxDynamicSharedMemorySize, GEMM_SMEM);
    cudaFuncSetAttribute(mma_gemm<1>, cudaFuncAttributeMaxDynamicSharedMemorySize, GEMM_SMEM);
    cudaFuncSetAttribute(mma_gemm<2>, cudaFuncAttributeMaxDynamicSharedMemorySize, GEMM_SMEM);

    c2half_kernel<<<1024, 256>>>(cb);
    init_best_kernel<<<64, 256>>>();
    cvt_planes_kernel<<<(384 * 1728 + 255) / 256, 256>>>(
        w2, (__nv_bfloat16*)pw2h, (__nv_bfloat16*)pw2l, 384 * 1728);
    cvt_planes_kernel<<<(768 * 3456 + 255) / 256, 256>>>(
        w3, (__nv_bfloat16*)pw3h, (__nv_bfloat16*)pw3l, 768 * 3456);
    cvt_planes_kernel<<<(8192 * 768 + 255) / 256, 256>>>(
        cb, (__nv_bfloat16*)pcbh, (__nv_bfloat16*)pcbl, 8192 * 768);
    conv1_kernel<<<512, 128>>>(image, w1, b1);

    // conv2: M=384 (w2 rows), N=65536 (spatial), K=1728
    mma_gemm<0><<<dim3(3, 512), 256, GEMM_SMEM>>>(
        pw2h, pw2l, pf1, nullptr, b2, pf2, nullptr, 1728);
    // conv3: M=16384 (tokens, gathered), N=768 (w3 rows), K=3456
    mma_gemm<1><<<dim3(128, 6), 256, GEMM_SMEM>>>(
        pf2, nullptr, pw3h, pw3l, b3, pf3h, pf3l, 3456);
    // distance: M=16384 (tokens), N=8192 (codes), K=768, fused argmax
    mma_gemm<2><<<dim3(128, 64), 256, GEMM_SMEM>>>(
        pf3h, pf3l, pcbh, pcbl, (const float*)pc2, nullptr, nullptr, 768);

    output_kernel<<<16384, 192>>>(tab, out);
}

// round 5
// speedup vs baseline: 2.3039x; 1.0140x over previous
#include <cuda_runtime.h>
#include <cuda_bf16.h>
#include <cstdint>

// ---------------------------------------------------------------------------
//   image [16,3,256,256] -> conv1 s2 relu -> g_f1i [16,192,128,128] {hi,lo} u32
//   conv2 s2 relu (bf16x3 mma) -> g_f2i [16,384,64,64] {hi,lo} u32
//   conv3 s2      (bf16x3 mma) -> g_f3h/g_f3l [16384][768] bf16 planes
//   distance GEMM (bf16x3 mma) + fused argmax -> g_best
//   R5: MMA term-reordering (acc RAW distance 1 -> 4), 4-stage cp.async.
// ---------------------------------------------------------------------------

__device__ uint32_t g_f1i[16u * 192u * 128u * 128u];
__device__ uint32_t g_f2i[16u * 384u * 64u * 64u];
__device__ __nv_bfloat16 g_f3h[16384u * 768u];
__device__ __nv_bfloat16 g_f3l[16384u * 768u];
__device__ __nv_bfloat16 g_w2h[384u * 1728u];
__device__ __nv_bfloat16 g_w2l[384u * 1728u];
__device__ __nv_bfloat16 g_w3h[768u * 3456u];
__device__ __nv_bfloat16 g_w3l[768u * 3456u];
__device__ __nv_bfloat16 g_cbh[8192u * 768u];
__device__ __nv_bfloat16 g_cbl[8192u * 768u];
__device__ float g_c2h[8192];
__device__ unsigned long long g_best[16384];

// ------------------------------ helpers -----------------------------------
__device__ __forceinline__ uint32_t smem_u32(const void* p) {
    uint32_t a;
    asm("{ .reg .u64 t; cvta.to.shared.u64 t, %1; cvt.u32.u64 %0, t; }"
        : "=r"(a) : "l"(p));
    return a;
}
__device__ __forceinline__ void ldsm4(uint32_t* r, uint32_t addr) {
    asm volatile("ldmatrix.sync.aligned.m8n8.x4.shared.b16 {%0,%1,%2,%3}, [%4];"
        : "=r"(r[0]), "=r"(r[1]), "=r"(r[2]), "=r"(r[3]) : "r"(addr));
}
__device__ __forceinline__ void mma_bf16(float* c, const uint32_t* a, const uint32_t* b) {
    asm volatile("mma.sync.aligned.m16n8k16.row.col.f32.bf16.bf16.f32 "
        "{%0,%1,%2,%3}, {%4,%5,%6,%7}, {%8,%9}, {%0,%1,%2,%3};"
        : "+f"(c[0]), "+f"(c[1]), "+f"(c[2]), "+f"(c[3])
        : "r"(a[0]), "r"(a[1]), "r"(a[2]), "r"(a[3]), "r"(b[0]), "r"(b[1]));
}
__device__ __forceinline__ uint32_t prmt(uint32_t a, uint32_t b, uint32_t c) {
    uint32_t d;
    asm("prmt.b32 %0, %1, %2, %3;" : "=r"(d) : "r"(a), "r"(b), "r"(c));
    return d;
}
__device__ __forceinline__ void cp16(uint32_t dst, const void* src) {
    asm volatile("cp.async.cg.shared.global [%0], [%1], 16;"
                 :: "r"(dst), "l"(src) : "memory");
}
__device__ __forceinline__ void sts128(uint32_t addr, uint32_t a, uint32_t b,
                                       uint32_t c, uint32_t d) {
    asm volatile("st.shared.v4.b32 [%0], {%1,%2,%3,%4};"
                 :: "r"(addr), "r"(a), "r"(b), "r"(c), "r"(d) : "memory");
}
__device__ __forceinline__ unsigned long long pack_key(float s, int v) {
    unsigned u = __float_as_uint(s);
    u = (u & 0x80000000u) ? ~u : (u | 0x80000000u);
    return ((unsigned long long)u << 32) | (unsigned)(0xFFFFFFFFu - (unsigned)v);
}
__device__ __forceinline__ uint32_t pack_hl(float v) {
    __nv_bfloat16 h = __float2bfloat16(v);
    float hf = __bfloat162float(h);
    __nv_bfloat16 l = __float2bfloat16(v - hf);
    return ((uint32_t)__bfloat16_as_ushort(l) << 16) | __bfloat16_as_ushort(h);
}

// ---------------------------------------------------------------------------
// bf16x3 mma GEMM. 128x128 tile, K-chunk 16, 4-stage cp.async pipeline.
//  MODE 0: conv2  A=w2 planes (direct), B=gather f1i, out f2i {hi,lo}+bias+relu
//  MODE 1: conv3  A=gather f2i,  B=w3 planes (direct), out f3 planes + bias
//  MODE 2: dist   A=f3 planes,   B=cb planes (direct), fused argmax
// ---------------------------------------------------------------------------
static constexpr int TILE = 128 * 48;      // 6144 B
static constexpr int STAGE = 4 * TILE;     // Ah,Al,Bh,Bl = 24576 B
static constexpr int NSTAGE = 4;
static constexpr int GEMM_SMEM = NSTAGE * STAGE + 512;

template<int MODE>
__global__ __launch_bounds__(256, 2) void mma_gemm(
    const void* __restrict__ pa0, const void* __restrict__ pa1,
    const void* __restrict__ pb0, const void* __restrict__ pb1,
    const float* __restrict__ vec, void* __restrict__ o0,
    void* __restrict__ o1, int K)
{
    extern __shared__ char sm[];
    const uint32_t sb = smem_u32(sm);
    const int tid = threadIdx.x, wid = tid >> 5, lane = tid & 31;
    const int m0 = blockIdx.x * 128, n0 = blockIdx.y * 128;
    const int NT = K >> 4;

    float* vecs = (float*)(sm + NSTAGE * STAGE);
    if (tid < 128) vecs[tid] = vec[(MODE == 0 ? m0 : n0) + tid];

    const int lrow = tid >> 1, lhalf = tid & 1;

    // ---- source setup
    const char* dirA_h = nullptr; const char* dirA_l = nullptr;
    const char* dirB_h = nullptr; const char* dirB_l = nullptr;
    const uint32_t* gsrc = nullptr;
    int giy0 = 0, gix0 = 0;

    if constexpr (MODE == 0) {
        dirA_h = (const char*)pa0 + ((size_t)(m0 + lrow) * 1728 + lhalf * 8) * 2;
        dirA_l = (const char*)pa1 + ((size_t)(m0 + lrow) * 1728 + lhalf * 8) * 2;
        int n = n0 + lrow;
        int bb = n >> 12, rem = n & 4095;
        int oy = rem >> 6, ox = rem & 63;
        gsrc = (const uint32_t*)pb0 + (size_t)bb * (192u * 128u * 128u);
        giy0 = 2 * oy - 1; gix0 = 2 * ox - 1;
    } else if constexpr (MODE == 1) {
        int n = m0 + lrow;
        int bb = n >> 10, rem = n & 1023;
        int oy = rem >> 5, ox = rem & 31;
        gsrc = (const uint32_t*)pa0 + (size_t)bb * (384u * 64u * 64u);
        giy0 = 2 * oy - 1; gix0 = 2 * ox - 1;
        dirB_h = (const char*)pb0 + ((size_t)(n0 + lrow) * 3456 + lhalf * 8) * 2;
        dirB_l = (const char*)pb1 + ((size_t)(n0 + lrow) * 3456 + lhalf * 8) * 2;
    } else {
        dirA_h = (const char*)pa0 + ((size_t)(m0 + lrow) * 768 + lhalf * 8) * 2;
        dirA_l = (const char*)pa1 + ((size_t)(m0 + lrow) * 768 + lhalf * 8) * 2;
        dirB_h = (const char*)pb0 + ((size_t)(n0 + lrow) * 768 + lhalf * 8) * 2;
        dirB_l = (const char*)pb1 + ((size_t)(n0 + lrow) * 768 + lhalf * 8) * 2;
    }

    const uint32_t loff = (uint32_t)(lrow * 48 + lhalf * 16);

    auto gather8 = [&](int kt, uint32_t dhi, uint32_t dlo, int HIN, int WIN) {
        uint32_t e[8];
        const int k0 = kt * 16 + lhalf * 8;
#pragma unroll
        for (int j = 0; j < 8; j++) {
            int k = k0 + j;
            int ci = (k * 7282) >> 16;     // k/9
            int r = k - ci * 9;
            int ky = (r * 11) >> 5;        // r/3
            int kx = r - ky * 3;
            int iy = giy0 + ky, ix = gix0 + kx;
            bool ok = (iy >= 0) && (iy < HIN) && (ix >= 0) && (ix < WIN);
            e[j] = ok ? gsrc[(size_t)((ci * HIN + iy) * WIN + ix)] : 0u;
        }
        sts128(dhi, prmt(e[0], e[1], 0x5410), prmt(e[2], e[3], 0x5410),
                    prmt(e[4], e[5], 0x5410), prmt(e[6], e[7], 0x5410));
        sts128(dlo, prmt(e[0], e[1], 0x7632), prmt(e[2], e[3], 0x7632),
                    prmt(e[4], e[5], 0x7632), prmt(e[6], e[7], 0x7632));
    };

    auto load_chunk = [&](int kt, int s) {
        const uint32_t st = sb + s * STAGE + loff;
        if constexpr (MODE == 0) {
            cp16(st,            dirA_h + kt * 32);
            cp16(st + TILE,     dirA_l + kt * 32);
            gather8(kt, st + 2 * TILE, st + 3 * TILE, 128, 128);
        } else if constexpr (MODE == 1) {
            gather8(kt, st, st + TILE, 64, 64);
            cp16(st + 2 * TILE, dirB_h + kt * 32);
            cp16(st + 3 * TILE, dirB_l + kt * 32);
        } else {
            cp16(st,            dirA_h + kt * 32);
            cp16(st + TILE,     dirA_l + kt * 32);
            cp16(st + 2 * TILE, dirB_h + kt * 32);
            cp16(st + 3 * TILE, dirB_l + kt * 32);
        }
        asm volatile("cp.async.commit_group;" ::: "memory");
    };

    // ---- warp tiling: 2 (m) x 4 (n), each warp 64x32
    const int wm = wid & 1, wn = wid >> 1;
    const int q = lane >> 3, rr = lane & 7;
    const uint32_t a_off = (uint32_t)((wm * 64 + (q & 1) * 8 + rr) * 48 + (q >> 1) * 16);
    const uint32_t b_off = (uint32_t)(((q >> 1) * 8 + rr) * 48 + (q & 1) * 16);

    float acc[4][4][4];
#pragma unroll
    for (int i = 0; i < 4; i++)
#pragma unroll
        for (int j = 0; j < 4; j++)
#pragma unroll
            for (int e = 0; e < 4; e++) acc[i][j][e] = 0.f;

    load_chunk(0, 0);
    load_chunk(1, 1);
    load_chunk(2, 2);

    for (int kt = 0; kt < NT; kt++) {
        const int s = kt & 3;
        if (kt + 2 < NT)
            asm volatile("cp.async.wait_group 2;" ::: "memory");
        else if (kt + 1 < NT)
            asm volatile("cp.async.wait_group 1;" ::: "memory");
        else
            asm volatile("cp.async.wait_group 0;" ::: "memory");
        __syncthreads();

        const uint32_t Ah_b = sb + s * STAGE;
        const uint32_t Al_b = Ah_b + TILE;
        const uint32_t Bh_b = Ah_b + 2 * TILE;
        const uint32_t Bl_b = Ah_b + 3 * TILE;

        uint32_t Bh[2][4], Bl[2][4];
        ldsm4(Bh[0], Bh_b + b_off + (wn * 32) * 48);
        ldsm4(Bh[1], Bh_b + b_off + (wn * 32 + 16) * 48);
        ldsm4(Bl[0], Bl_b + b_off + (wn * 32) * 48);
        ldsm4(Bl[1], Bl_b + b_off + (wn * 32 + 16) * 48);
#pragma unroll
        for (int mi = 0; mi < 4; mi++) {
            uint32_t Ah[4], Al[4];
            ldsm4(Ah, Ah_b + a_off + mi * 16 * 48);
            ldsm4(Al, Al_b + a_off + mi * 16 * 48);
            // term-major ordering: same accumulator reused at distance 4
#pragma unroll
            for (int nj = 0; nj < 4; nj++)
                mma_bf16(acc[mi][nj], Ah, &Bh[nj >> 1][(nj & 1) * 2]);   // hi*hi
#pragma unroll
            for (int nj = 0; nj < 4; nj++)
                mma_bf16(acc[mi][nj], Ah, &Bl[nj >> 1][(nj & 1) * 2]);   // hi*lo
#pragma unroll
            for (int nj = 0; nj < 4; nj++)
                mma_bf16(acc[mi][nj], Al, &Bh[nj >> 1][(nj & 1) * 2]);   // lo*hi
        }

        if (kt + 3 < NT) load_chunk(kt + 3, (kt + 3) & 3);
    }

    // ---- epilogue. Fragment c[e]: rows tg(+8), cols 2*tp + e%2
    const int tg = lane >> 2, tp = lane & 3;

    if constexpr (MODE == 0) {
        uint32_t* Ci = (uint32_t*)o0;
        const int bb = n0 >> 12;
        const int sp0 = (n0 & 4095) + wn * 32;
#pragma unroll
        for (int mi = 0; mi < 4; mi++)
#pragma unroll
            for (int h = 0; h < 2; h++) {
                int ml = wm * 64 + mi * 16 + tg + h * 8;
                int m = m0 + ml;
                float bv = vecs[ml];
                uint32_t* rowp = Ci + ((size_t)bb * 384 + m) * 4096;
#pragma unroll
                for (int nj = 0; nj < 4; nj++) {
                    float v0 = fmaxf(acc[mi][nj][h * 2 + 0] + bv, 0.f);
                    float v1 = fmaxf(acc[mi][nj][h * 2 + 1] + bv, 0.f);
                    *(uint2*)(rowp + sp0 + nj * 8 + 2 * tp) =
                        make_uint2(pack_hl(v0), pack_hl(v1));
                }
            }
    } else if constexpr (MODE == 1) {
        __nv_bfloat16* fh = (__nv_bfloat16*)o0;
        __nv_bfloat16* fl = (__nv_bfloat16*)o1;
#pragma unroll
        for (int mi = 0; mi < 4; mi++)
#pragma unroll
            for (int h = 0; h < 2; h++) {
                int m = m0 + wm * 64 + mi * 16 + tg + h * 8;   // token
                __nv_bfloat16* rowh = fh + (size_t)m * 768 + n0;
                __nv_bfloat16* rowl = fl + (size_t)m * 768 + n0;
#pragma unroll
                for (int nj = 0; nj < 4; nj++) {
                    int nl = wn * 32 + nj * 8 + 2 * tp;
                    float v0 = acc[mi][nj][h * 2 + 0] + vecs[nl + 0];
                    float v1 = acc[mi][nj][h * 2 + 1] + vecs[nl + 1];
                    __nv_bfloat16 h0 = __float2bfloat16(v0);
                    __nv_bfloat16 h1 = __float2bfloat16(v1);
                    __nv_bfloat16 l0 = __float2bfloat16(v0 - __bfloat162float(h0));
                    __nv_bfloat16 l1 = __float2bfloat16(v1 - __bfloat162float(h1));
                    *(__nv_bfloat162*)(rowh + nl) = __nv_bfloat162(h0, h1);
                    *(__nv_bfloat162*)(rowl + nl) = __nv_bfloat162(l0, l1);
                }
            }
    } else {
#pragma unroll
        for (int mi = 0; mi < 4; mi++)
#pragma unroll
            for (int h = 0; h < 2; h++) {
                int m = m0 + wm * 64 + mi * 16 + tg + h * 8;   // token
                unsigned long long best = 0ull;
#pragma unroll
                for (int nj = 0; nj < 4; nj++)
#pragma unroll
                    for (int e = 0; e < 2; e++) {
                        int nl = wn * 32 + nj * 8 + 2 * tp + e;
                        float sc = acc[mi][nj][h * 2 + e] - vecs[nl];
                        unsigned long long key = pack_key(sc, n0 + nl);
                        best = key > best ? key : best;
                    }
                unsigned long long o = __shfl_xor_sync(0xFFFFFFFFu, best, 1);
                best = best > o ? best : o;
                o = __shfl_xor_sync(0xFFFFFFFFu, best, 2);
                best = best > o ? best : o;
                if (tp == 0) atomicMax(&g_best[m], best);
            }
    }
}

// ---------------------------------------------------------------------------
// conv1: Cin=3, 3x3 s2 pad1, relu -> interleaved {hi,lo} uint32 NCHW
// ---------------------------------------------------------------------------
__global__ __launch_bounds__(128) void conv1_kernel(
    const float* __restrict__ in, const float* __restrict__ w,
    const float* __restrict__ bias)
{
    __shared__ float Ws[192 * 27];
    __shared__ float Bsm[192];
    for (int i = threadIdx.x; i < 192 * 27; i += 128) Ws[i] = w[i];
    for (int i = threadIdx.x; i < 192; i += 128) Bsm[i] = bias[i];
    __syncthreads();

    int g = blockIdx.x * 128 + threadIdx.x;
    int x0 = (g & 31) * 4;
    int y = (g >> 5) & 127;
    int b = g >> 12;

    float xv[3][3][9];
    int iy0 = 2 * y - 1;
    int ix0 = 2 * x0 - 1;
#pragma unroll
    for (int ci = 0; ci < 3; ci++)
#pragma unroll
        for (int ky = 0; ky < 3; ky++) {
            int iy = iy0 + ky;
            bool yok = (iy >= 0) && (iy < 256);
            const float* rowp = in + (((size_t)b * 3 + ci) * 256 + iy) * 256;
#pragma unroll
            for (int c = 0; c < 9; c++) {
                int ix = ix0 + c;
                xv[ci][ky][c] = (yok && ix >= 0 && ix < 256) ? rowp[ix] : 0.f;
            }
        }

    uint32_t* outp = g_f1i + (size_t)b * 192 * 16384 + y * 128 + x0;
    for (int co = 0; co < 192; co++) {
        float bv = Bsm[co];
        float a0 = bv, a1 = bv, a2 = bv, a3 = bv;
        const float* wp = &Ws[co * 27];
#pragma unroll
        for (int ci = 0; ci < 3; ci++)
#pragma unroll
            for (int ky = 0; ky < 3; ky++)
#pragma unroll
                for (int kx = 0; kx < 3; kx++) {
                    float wv = wp[ci * 9 + ky * 3 + kx];
                    a0 = fmaf(wv, xv[ci][ky][0 + kx], a0);
                    a1 = fmaf(wv, xv[ci][ky][2 + kx], a1);
                    a2 = fmaf(wv, xv[ci][ky][4 + kx], a2);
                    a3 = fmaf(wv, xv[ci][ky][6 + kx], a3);
                }
        uint4 r;
        r.x = pack_hl(fmaxf(a0, 0.f));
        r.y = pack_hl(fmaxf(a1, 0.f));
        r.z = pack_hl(fmaxf(a2, 0.f));
        r.w = pack_hl(fmaxf(a3, 0.f));
        *(uint4*)(outp + (size_t)co * 16384) = r;
    }
}

// ---------------------------------------------------------------------------
__global__ void cvt_planes_kernel(const float* __restrict__ src,
                                  __nv_bfloat16* __restrict__ hi,
                                  __nv_bfloat16* __restrict__ lo, int n)
{
    int i = blockIdx.x * 256 + threadIdx.x;
    if (i >= n) return;
    float v = src[i];
    __nv_bfloat16 h = __float2bfloat16(v);
    hi[i] = h;
    lo[i] = __float2bfloat16(v - __bfloat162float(h));
}

// c2half + g_best init fused
__global__ void c2half_kernel(const float* __restrict__ cb) {
    int gt = blockIdx.x * 256 + threadIdx.x;
    if (gt < 16384) g_best[gt] = 0ULL;
    int v = blockIdx.x * 8 + (threadIdx.x >> 5);
    int lane = threadIdx.x & 31;
    const float* row = cb + (size_t)v * 768;
    float s = 0.f;
    for (int c = lane; c < 768; c += 32) { float t = row[c]; s = fmaf(t, t, s); }
#pragma unroll
    for (int o = 16; o > 0; o >>= 1) s += __shfl_xor_sync(0xFFFFFFFFu, s, o);
    if (lane == 0) g_c2h[v] = 0.5f * s;
}

__global__ __launch_bounds__(192) void output_kernel(
    const float* __restrict__ table, float* __restrict__ out)
{
    int p = blockIdx.x;
    unsigned long long key = g_best[p];
    unsigned v = 0xFFFFFFFFu - (unsigned)(key & 0xFFFFFFFFu);
    if (threadIdx.x == 0) out[p] = (float)v;
    float4* dst = (float4*)(out + 16384 + (size_t)p * 768);
    const float4* src = (const float4*)(table + (size_t)v * 768);
    dst[threadIdx.x] = src[threadIdx.x];
}

// ---------------------------------------------------------------------------
extern "C" void kernel_launch(void* const* d_in, const int* in_sizes, int n_in,
                              void* d_out, int out_size)
{
    (void)in_sizes; (void)n_in; (void)out_size;
    const float* image = (const float*)d_in[0];
    const float* w1 = (const float*)d_in[1];
    const float* b1 = (const float*)d_in[2];
    const float* w2 = (const float*)d_in[3];
    const float* b2 = (const float*)d_in[4];
    const float* w3 = (const float*)d_in[5];
    const float* b3 = (const float*)d_in[6];
    const float* cb = (const float*)d_in[7];
    const float* tab = (const float*)d_in[8];
    float* out = (float*)d_out;

    void *pf1, *pf2, *pf3h, *pf3l, *pw2h, *pw2l, *pw3h, *pw3l, *pcbh, *pcbl, *pc2;
    cudaGetSymbolAddress(&pf1, g_f1i);
    cudaGetSymbolAddress(&pf2, g_f2i);
    cudaGetSymbolAddress(&pf3h, g_f3h);
    cudaGetSymbolAddress(&pf3l, g_f3l);
    cudaGetSymbolAddress(&pw2h, g_w2h);
    cudaGetSymbolAddress(&pw2l, g_w2l);
    cudaGetSymbolAddress(&pw3h, g_w3h);
    cudaGetSymbolAddress(&pw3l, g_w3l);
    cudaGetSymbolAddress(&pcbh, g_cbh);
    cudaGetSymbolAddress(&pcbl, g_cbl);
    cudaGetSymbolAddress(&pc2, g_c2h);

    cudaFuncSetAttribute(mma_gemm<0>, cudaFuncAttributeMaxDynamicSharedMemorySize, GEMM_SMEM);
    cudaFuncSetAttribute(mma_gemm<1>, cudaFuncAttributeMaxDynamicSharedMemorySize, GEMM_SMEM);
    cudaFuncSetAttribute(mma_gemm<2>, cudaFuncAttributeMaxDynamicSharedMemorySize, GEMM_SMEM);

    c2half_kernel<<<1024, 256>>>(cb);
    cvt_planes_kernel<<<(384 * 1728 + 255) / 256, 256>>>(
        w2, (__nv_bfloat16*)pw2h, (__nv_bfloat16*)pw2l, 384 * 1728);
    cvt_planes_kernel<<<(768 * 3456 + 255) / 256, 256>>>(
        w3, (__nv_bfloat16*)pw3h, (__nv_bfloat16*)pw3l, 768 * 3456);
    cvt_planes_kernel<<<(8192 * 768 + 255) / 256, 256>>>(
        cb, (__nv_bfloat16*)pcbh, (__nv_bfloat16*)pcbl, 8192 * 768);
    conv1_kernel<<<512, 128>>>(image, w1, b1);

    // conv2: M=384 (w2 rows), N=65536 (spatial), K=1728
    mma_gemm<0><<<dim3(3, 512), 256, GEMM_SMEM>>>(
        pw2h, pw2l, pf1, nullptr, b2, pf2, nullptr, 1728);
    // conv3: M=16384 (tokens, gathered), N=768 (w3 rows), K=3456
    mma_gemm<1><<<dim3(128, 6), 256, GEMM_SMEM>>>(
        pf2, nullptr, pw3h, pw3l, b3, pf3h, pf3l, 3456);
    // distance: M=16384 (tokens), N=8192 (codes), K=768, fused argmax
    mma_gemm<2><<<dim3(128, 64), 256, GEMM_SMEM>>>(
        pf3h, pf3l, pcbh, pcbl, (const float*)pc2, nullptr, nullptr, 768);

    output_kernel<<<16384, 192>>>(tab, out);
}